// round 1
// baseline (speedup 1.0000x reference)
#include <cuda_runtime.h>
#include <cuda_bf16.h>

// Problem constants
#define NB 16
#define NC 128
#define NT 128
#define NH 128
#define BC (NB * NC)          // 2048
#define KT 16                 // k-tile
#define SA_STRIDE 132         // padded stride for transposed A tile

// ---------------------------------------------------------------------------
// Scratch (static device globals; no runtime allocation allowed)
// ---------------------------------------------------------------------------
__device__ float g_base_thorn[BC * NH];       // clone @ W_thorn[:H]
__device__ float g_A1[BC * NH];               // clone @ W_clone[:H]
__device__ float g_A2[BC * NH];               // clone @ W_clone[H:2H]
__device__ float g_thorn_agg[BC * NH];
__device__ float g_clone_agg[BC * NH];
__device__ float g_aggbuf[BC * 4 * NH];       // concat buffer (2048 x 512)
__device__ float g_partial[4 * BC * NH];      // final GEMM k-slice partials

// ---------------------------------------------------------------------------
// Shared block GEMM: one 128x128 output tile, K=128, fp32.
// 256 threads as 16x16 grid, each computes an 8x8 register tile.
// A: row-major, lda given (caller pre-offsets to the tile's top-left).
// Bm: 128x128 row-major [k][n].
// ---------------------------------------------------------------------------
__device__ __forceinline__ void gemm_block_k128(
    const float* __restrict__ A, int lda,
    const float* __restrict__ Bm,
    float* sA, float* sB, float acc[8][8])
{
    const int tid = threadIdx.x;
    const int tx = tid & 15;
    const int ty = tid >> 4;

#pragma unroll
    for (int i = 0; i < 8; i++)
#pragma unroll
        for (int j = 0; j < 8; j++) acc[i][j] = 0.0f;

    for (int k0 = 0; k0 < 128; k0 += KT) {
        __syncthreads();
        // Load A tile (128 rows x 16 k), store transposed: sA[k][t]
#pragma unroll
        for (int r = 0; r < 8; r++) {
            int idx = tid + r * 256;          // 0..2047
            int t = idx >> 4;
            int k = idx & 15;
            sA[k * SA_STRIDE + t] = A[(size_t)t * lda + k0 + k];
        }
        // Load B tile (16 k x 128 n): sB[k][n]
#pragma unroll
        for (int r = 0; r < 8; r++) {
            int idx = tid + r * 256;
            int k = idx >> 7;
            int n = idx & 127;
            sB[k * 128 + n] = Bm[(size_t)(k0 + k) * 128 + n];
        }
        __syncthreads();

#pragma unroll
        for (int kk = 0; kk < KT; kk++) {
            float4 a0 = *(const float4*)&sA[kk * SA_STRIDE + ty * 8];
            float4 a1 = *(const float4*)&sA[kk * SA_STRIDE + ty * 8 + 4];
            float4 b0 = *(const float4*)&sB[kk * 128 + tx * 8];
            float4 b1 = *(const float4*)&sB[kk * 128 + tx * 8 + 4];
            float a[8] = {a0.x, a0.y, a0.z, a0.w, a1.x, a1.y, a1.z, a1.w};
            float b[8] = {b0.x, b0.y, b0.z, b0.w, b1.x, b1.y, b1.z, b1.w};
#pragma unroll
            for (int i = 0; i < 8; i++)
#pragma unroll
                for (int j = 0; j < 8; j++)
                    acc[i][j] = fmaf(a[i], b[j], acc[i][j]);
        }
    }
}

// ---------------------------------------------------------------------------
// Precompute: three GEMMs clone(2048x128) @ W(128x128), selected by blockIdx.y
//   y=0: W_thorn[:H]      -> g_base_thorn
//   y=1: W_clone[:H]      -> g_A1
//   y=2: W_clone[H:2H]    -> g_A2
// ---------------------------------------------------------------------------
__global__ void __launch_bounds__(256) precompute_kernel(
    const float* __restrict__ clone,
    const float* __restrict__ W_thorn,
    const float* __restrict__ W_clone)
{
    __shared__ float sA[KT * SA_STRIDE];
    __shared__ float sB[KT * 128];

    const float* Bm;
    float* out;
    if (blockIdx.y == 0)      { Bm = W_thorn;              out = g_base_thorn; }
    else if (blockIdx.y == 1) { Bm = W_clone;              out = g_A1; }
    else                      { Bm = W_clone + 128 * 128;  out = g_A2; }

    const int m0 = blockIdx.x * 128;
    float acc[8][8];
    gemm_block_k128(clone + (size_t)m0 * 128, 128, Bm, sA, sB, acc);

    const int tid = threadIdx.x;
    const int tx = tid & 15;
    const int ty = tid >> 4;
#pragma unroll
    for (int i = 0; i < 8; i++) {
        int row = m0 + ty * 8 + i;
        float4 v0 = make_float4(acc[i][0], acc[i][1], acc[i][2], acc[i][3]);
        float4 v1 = make_float4(acc[i][4], acc[i][5], acc[i][6], acc[i][7]);
        *(float4*)&out[(size_t)row * 128 + tx * 8]     = v0;
        *(float4*)&out[(size_t)row * 128 + tx * 8 + 4] = v1;
    }
}

// ---------------------------------------------------------------------------
// Relation kernel: one block per (b,c). Computes
//   X[t][n] = rel[b,c,t,:] @ W2[:,n]  (128x128x128 GEMM)
// then epilogue: x += base_col[n] (+ rowTerm[b,row][n] in clone mode) + bias[n]
//   val = relu(x) * mask[b,row];  out[b,c,n] = max over rows.
// relu*mask >= 0, so max-accumulator init 0 is exact.
// ---------------------------------------------------------------------------
template<bool CLONE_MODE>
__global__ void __launch_bounds__(256) relation_kernel(
    const float* __restrict__ rel,
    const float* __restrict__ W2,
    const float* __restrict__ bias,
    const int* __restrict__ mask)
{
    __shared__ float sA[KT * SA_STRIDE];
    __shared__ float sB[KT * 128];

    const int bc = blockIdx.x;
    const int b = bc >> 7;

    const float* baseCol = CLONE_MODE ? g_A1 : g_base_thorn;
    float* out = CLONE_MODE ? g_clone_agg : g_thorn_agg;

    float acc[8][8];
    gemm_block_k128(rel + (size_t)bc * 128 * 128, 128, W2, sA, sB, acc);

    const int tid = threadIdx.x;
    const int tx = tid & 15;
    const int ty = tid >> 4;

    float base[8];
#pragma unroll
    for (int j = 0; j < 8; j++)
        base[j] = baseCol[(size_t)bc * 128 + tx * 8 + j] + bias[tx * 8 + j];

    float pmax[8];
#pragma unroll
    for (int j = 0; j < 8; j++) pmax[j] = 0.0f;

#pragma unroll
    for (int i = 0; i < 8; i++) {
        int row = ty * 8 + i;
        float m = (float)mask[b * 128 + row];
        if (CLONE_MODE) {
            const float* rt = g_A2 + ((size_t)(b * 128 + row)) * 128 + tx * 8;
#pragma unroll
            for (int j = 0; j < 8; j++) {
                float x = acc[i][j] + base[j] + rt[j];
                pmax[j] = fmaxf(pmax[j], fmaxf(x, 0.0f) * m);
            }
        } else {
#pragma unroll
            for (int j = 0; j < 8; j++) {
                float x = acc[i][j] + base[j];
                pmax[j] = fmaxf(pmax[j], fmaxf(x, 0.0f) * m);
            }
        }
    }

    // Cross-ty max reduction via smem (reuse sB: 16*128 floats)
    __syncthreads();
    float* red = sB;
    *(float4*)&red[ty * 128 + tx * 8]     = make_float4(pmax[0], pmax[1], pmax[2], pmax[3]);
    *(float4*)&red[ty * 128 + tx * 8 + 4] = make_float4(pmax[4], pmax[5], pmax[6], pmax[7]);
    __syncthreads();

    if (tid < 128) {
        float m = 0.0f;
#pragma unroll
        for (int i = 0; i < 16; i++) m = fmaxf(m, red[i * 128 + tid]);
        out[(size_t)bc * 128 + tid] = m;
    }
}

// ---------------------------------------------------------------------------
// Concat: aggbuf[bc, 0:512] = [clone, food, thorn_agg, clone_agg]
// ---------------------------------------------------------------------------
__global__ void __launch_bounds__(256) concat_kernel(
    const float* __restrict__ clone,
    const float* __restrict__ food)
{
    int idx = blockIdx.x * 256 + threadIdx.x;   // 0 .. 2048*512-1
    int bc = idx >> 9;
    int col = idx & 511;
    int h = col & 127;
    float v;
    switch (col >> 7) {
        case 0:  v = clone[(size_t)bc * 128 + h]; break;
        case 1:  v = food[(size_t)bc * 128 + h]; break;
        case 2:  v = g_thorn_agg[(size_t)bc * 128 + h]; break;
        default: v = g_clone_agg[(size_t)bc * 128 + h]; break;
    }
    g_aggbuf[idx] = v;
}

// ---------------------------------------------------------------------------
// Final GEMM, K split in 4 slices of 128: partial[y] = agg[:, y*128:(y+1)*128] @ W_agg[y*128:...]
// ---------------------------------------------------------------------------
__global__ void __launch_bounds__(256) final_partial_kernel(
    const float* __restrict__ W_agg)
{
    __shared__ float sA[KT * SA_STRIDE];
    __shared__ float sB[KT * 128];

    const int y = blockIdx.y;
    const int m0 = blockIdx.x * 128;
    const float* A = g_aggbuf + (size_t)m0 * 512 + y * 128;
    const float* Bm = W_agg + (size_t)y * 128 * 128;
    float* out = g_partial + (size_t)y * BC * 128;

    float acc[8][8];
    gemm_block_k128(A, 512, Bm, sA, sB, acc);

    const int tid = threadIdx.x;
    const int tx = tid & 15;
    const int ty = tid >> 4;
#pragma unroll
    for (int i = 0; i < 8; i++) {
        int row = m0 + ty * 8 + i;
        float4 v0 = make_float4(acc[i][0], acc[i][1], acc[i][2], acc[i][3]);
        float4 v1 = make_float4(acc[i][4], acc[i][5], acc[i][6], acc[i][7]);
        *(float4*)&out[(size_t)row * 128 + tx * 8]     = v0;
        *(float4*)&out[(size_t)row * 128 + tx * 8 + 4] = v1;
    }
}

// ---------------------------------------------------------------------------
// Combine: out = clone + relu(sum_partials + b_agg)
// ---------------------------------------------------------------------------
__global__ void __launch_bounds__(256) combine_kernel(
    const float* __restrict__ clone,
    const float* __restrict__ b_agg,
    float* __restrict__ out)
{
    int idx = blockIdx.x * 256 + threadIdx.x;   // 0 .. 262143
    int n = idx & 127;
    float s = g_partial[idx]
            + g_partial[BC * 128 + idx]
            + g_partial[2 * BC * 128 + idx]
            + g_partial[3 * BC * 128 + idx]
            + b_agg[n];
    out[idx] = clone[idx] + fmaxf(s, 0.0f);
}

// ---------------------------------------------------------------------------
// Launch
// ---------------------------------------------------------------------------
extern "C" void kernel_launch(void* const* d_in, const int* in_sizes, int n_in,
                              void* d_out, int out_size)
{
    const float* food       = (const float*)d_in[0];
    const float* thorn_rel  = (const float*)d_in[1];
    const float* clone      = (const float*)d_in[2];
    const float* clone_rel  = (const float*)d_in[3];
    const int*   thorn_mask = (const int*)d_in[4];
    const int*   clone_mask = (const int*)d_in[5];
    const float* W_thorn    = (const float*)d_in[6];
    const float* b_thorn    = (const float*)d_in[7];
    const float* W_clone    = (const float*)d_in[8];
    const float* b_clone    = (const float*)d_in[9];
    const float* W_agg      = (const float*)d_in[10];
    const float* b_agg      = (const float*)d_in[11];
    float* out = (float*)d_out;

    // 1. Precompute clone @ {W_thorn[:H], W_clone[:H], W_clone[H:2H]}
    precompute_kernel<<<dim3(16, 3), 256>>>(clone, W_thorn, W_clone);

    // 2. Thorn branch (W_thorn rows H..2H)
    relation_kernel<false><<<BC, 256>>>(thorn_rel, W_thorn + 128 * 128,
                                        b_thorn, thorn_mask);
    // 3. Clone branch (W_clone rows 2H..3H)
    relation_kernel<true><<<BC, 256>>>(clone_rel, W_clone + 2 * 128 * 128,
                                       b_clone, clone_mask);

    // 4. Concat into (2048, 512) buffer
    concat_kernel<<<(BC * 512) / 256, 256>>>(clone, food);

    // 5. Final GEMM (K=512 split into 4 slices of 128)
    final_partial_kernel<<<dim3(16, 4), 256>>>(W_agg);

    // 6. Combine partials + bias, relu, residual add
    combine_kernel<<<(BC * 128) / 256, 256>>>(clone, b_agg, out);
}

// round 2
// speedup vs baseline: 1.6235x; 1.6235x over previous
#include <cuda_runtime.h>
#include <cuda_bf16.h>
#include <cstdint>

// Problem constants
#define NB 16
#define NC 128
#define NT 128
#define NH 128
#define BC (NB * NC)          // 2048
#define KT 16                 // k-tile for fp32 gemm
#define SA_STRIDE 132         // padded stride for fp32 gemm A tile

// ---------------------------------------------------------------------------
// Scratch (static device globals; no runtime allocation allowed)
// ---------------------------------------------------------------------------
__device__ float g_base_thorn[BC * NH];       // clone @ W_thorn[:H]
__device__ float g_A1[BC * NH];               // clone @ W_clone[:H]
__device__ float g_A2[BC * NH];               // clone @ W_clone[H:2H]
__device__ float g_thorn_agg[BC * NH];
__device__ float g_clone_agg[BC * NH];
__device__ float g_partial[4 * BC * NH];      // final GEMM k-slice partials
// Prepacked TF32 B fragments for the two relation weights:
// layout [branch][ ((ks*16 + nt)*32 + lane)*2 + j ]
__device__ uint32_t g_Bpack[2][16 * 16 * 32 * 2];

// ---------------------------------------------------------------------------
// fp32 block GEMM (used for the small exact GEMMs): 128x128 tile, K=128.
// 256 threads as 16x16, each 8x8 register tile.
// ---------------------------------------------------------------------------
__device__ __forceinline__ void gemm_block_k128(
    const float* __restrict__ A, int lda,
    const float* __restrict__ Bm,
    float* sA, float* sB, float acc[8][8])
{
    const int tid = threadIdx.x;
    const int tx = tid & 15;
    const int ty = tid >> 4;

#pragma unroll
    for (int i = 0; i < 8; i++)
#pragma unroll
        for (int j = 0; j < 8; j++) acc[i][j] = 0.0f;

    for (int k0 = 0; k0 < 128; k0 += KT) {
        __syncthreads();
#pragma unroll
        for (int r = 0; r < 8; r++) {
            int idx = tid + r * 256;
            int t = idx >> 4;
            int k = idx & 15;
            sA[k * SA_STRIDE + t] = A[(size_t)t * lda + k0 + k];
        }
#pragma unroll
        for (int r = 0; r < 8; r++) {
            int idx = tid + r * 256;
            int k = idx >> 7;
            int n = idx & 127;
            sB[k * 128 + n] = Bm[(size_t)(k0 + k) * 128 + n];
        }
        __syncthreads();

#pragma unroll
        for (int kk = 0; kk < KT; kk++) {
            float4 a0 = *(const float4*)&sA[kk * SA_STRIDE + ty * 8];
            float4 a1 = *(const float4*)&sA[kk * SA_STRIDE + ty * 8 + 4];
            float4 b0 = *(const float4*)&sB[kk * 128 + tx * 8];
            float4 b1 = *(const float4*)&sB[kk * 128 + tx * 8 + 4];
            float a[8] = {a0.x, a0.y, a0.z, a0.w, a1.x, a1.y, a1.z, a1.w};
            float b[8] = {b0.x, b0.y, b0.z, b0.w, b1.x, b1.y, b1.z, b1.w};
#pragma unroll
            for (int i = 0; i < 8; i++)
#pragma unroll
                for (int j = 0; j < 8; j++)
                    acc[i][j] = fmaf(a[i], b[j], acc[i][j]);
        }
    }
}

// ---------------------------------------------------------------------------
// Precompute: clone(2048x128) @ {W_thorn[:H], W_clone[:H], W_clone[H:2H]}
// ---------------------------------------------------------------------------
__global__ void __launch_bounds__(256) precompute_kernel(
    const float* __restrict__ clone,
    const float* __restrict__ W_thorn,
    const float* __restrict__ W_clone)
{
    __shared__ float sA[KT * SA_STRIDE];
    __shared__ float sB[KT * 128];

    const float* Bm;
    float* out;
    if (blockIdx.y == 0)      { Bm = W_thorn;              out = g_base_thorn; }
    else if (blockIdx.y == 1) { Bm = W_clone;              out = g_A1; }
    else                      { Bm = W_clone + 128 * 128;  out = g_A2; }

    const int m0 = blockIdx.x * 128;
    float acc[8][8];
    gemm_block_k128(clone + (size_t)m0 * 128, 128, Bm, sA, sB, acc);

    const int tid = threadIdx.x;
    const int tx = tid & 15;
    const int ty = tid >> 4;
#pragma unroll
    for (int i = 0; i < 8; i++) {
        int row = m0 + ty * 8 + i;
        *(float4*)&out[(size_t)row * 128 + tx * 8] =
            make_float4(acc[i][0], acc[i][1], acc[i][2], acc[i][3]);
        *(float4*)&out[(size_t)row * 128 + tx * 8 + 4] =
            make_float4(acc[i][4], acc[i][5], acc[i][6], acc[i][7]);
    }
}

// ---------------------------------------------------------------------------
// Prepack the relation weights into TF32 mma B-fragment order.
// branch 0: W_thorn rows [H,2H); branch 1: W_clone rows [2H,3H).
// For kstep ks, ntile nt, lane l (g=l>>2, t4=l&3):
//   b0 = W[ks*8 + t4    ][nt*8 + g]
//   b1 = W[ks*8 + t4 + 4][nt*8 + g]
// ---------------------------------------------------------------------------
__global__ void __launch_bounds__(256) prepack_kernel(
    const float* __restrict__ W_thorn,
    const float* __restrict__ W_clone)
{
    int branch = blockIdx.y;
    const float* W = branch ? (W_clone + 2 * 128 * 128) : (W_thorn + 128 * 128);
    int idx = blockIdx.x * 256 + threadIdx.x;    // 0..16383
    int j    = idx & 1;
    int lane = (idx >> 1) & 31;
    int nt   = (idx >> 6) & 15;
    int ks   = idx >> 10;
    int t4 = lane & 3, g = lane >> 2;
    int k = ks * 8 + t4 + j * 4;
    int n = nt * 8 + g;
    float v = W[k * 128 + n];
    uint32_t u;
    asm("cvt.rna.tf32.f32 %0, %1;" : "=r"(u) : "f"(v));
    g_Bpack[branch][idx] = u;
}

// ---------------------------------------------------------------------------
// TF32 tensor-core relation kernel. One block per (bc, branch).
//   X[t][n] = rel[bc,t,:] @ W2  (128x128x128)
//   x = X + base[n] (+ rowterm[row][n] in clone branch)
//   out[bc][n] = max_t relu(x) * mask[b,t]        (init 0 is exact)
// 256 threads = 8 warps; warp w owns rows [16w,16w+16), all 128 cols.
// ---------------------------------------------------------------------------
__global__ void __launch_bounds__(256) relation_mma_kernel(
    const float* __restrict__ thorn_rel,
    const float* __restrict__ clone_rel,
    const float* __restrict__ b_thorn,
    const float* __restrict__ b_clone,
    const int* __restrict__ thorn_mask,
    const int* __restrict__ clone_mask)
{
    __shared__ uint32_t sA[128 * 36];        // A chunk: 128 rows x 32 k, stride 36
    __shared__ float red[8 * 128];           // cross-warp column-max buffer

    const int bc = blockIdx.x;
    const int branch = blockIdx.y;           // 0 = thorn, 1 = clone
    const int b = bc >> 7;

    const float* rel = branch ? clone_rel : thorn_rel;
    const float* bias = branch ? b_clone : b_thorn;
    const int* mask = branch ? clone_mask : thorn_mask;
    const float* baseCol = branch ? g_A1 : g_base_thorn;
    float* out = branch ? g_clone_agg : g_thorn_agg;
    const uint32_t* __restrict__ Bp = g_Bpack[branch];

    const int tid = threadIdx.x;
    const int warp = tid >> 5;
    const int lane = tid & 31;
    const int g = lane >> 2;
    const int t4 = lane & 3;
    const int wrow = warp * 16;

    const float* Atile = rel + (size_t)bc * 128 * 128;

    float acc[16][4];
#pragma unroll
    for (int nt = 0; nt < 16; nt++)
#pragma unroll
        for (int c = 0; c < 4; c++) acc[nt][c] = 0.0f;

    for (int ch = 0; ch < 4; ch++) {
        const int k0 = ch * 32;
        __syncthreads();
        // Stage A chunk (128 x 32 fp32 -> tf32) into smem, stride 36.
#pragma unroll
        for (int r = 0; r < 4; r++) {
            int idx = tid + r * 256;          // 0..1023
            int row = idx >> 3;
            int cg = idx & 7;
            float4 v = *(const float4*)&Atile[(size_t)row * 128 + k0 + cg * 4];
            uint4 u;
            asm("cvt.rna.tf32.f32 %0, %1;" : "=r"(u.x) : "f"(v.x));
            asm("cvt.rna.tf32.f32 %0, %1;" : "=r"(u.y) : "f"(v.y));
            asm("cvt.rna.tf32.f32 %0, %1;" : "=r"(u.z) : "f"(v.z));
            asm("cvt.rna.tf32.f32 %0, %1;" : "=r"(u.w) : "f"(v.w));
            *(uint4*)&sA[row * 36 + cg * 4] = u;
        }
        __syncthreads();

#pragma unroll
        for (int kk = 0; kk < 4; kk++) {
            const int ks = ch * 4 + kk;
            uint32_t a0 = sA[(wrow + g) * 36 + kk * 8 + t4];
            uint32_t a1 = sA[(wrow + g + 8) * 36 + kk * 8 + t4];
            uint32_t a2 = sA[(wrow + g) * 36 + kk * 8 + t4 + 4];
            uint32_t a3 = sA[(wrow + g + 8) * 36 + kk * 8 + t4 + 4];
            const uint32_t* bbase = Bp + ks * 1024 + lane * 2;
#pragma unroll
            for (int nt = 0; nt < 16; nt++) {
                uint2 bb = *(const uint2*)&bbase[nt * 64];
                asm volatile(
                    "mma.sync.aligned.m16n8k8.row.col.f32.tf32.tf32.f32 "
                    "{%0,%1,%2,%3}, {%4,%5,%6,%7}, {%8,%9}, {%0,%1,%2,%3};"
                    : "+f"(acc[nt][0]), "+f"(acc[nt][1]),
                      "+f"(acc[nt][2]), "+f"(acc[nt][3])
                    : "r"(a0), "r"(a1), "r"(a2), "r"(a3),
                      "r"(bb.x), "r"(bb.y));
            }
        }
    }

    // Epilogue: rows r0 = wrow+g, r1 = wrow+g+8; cols n0 = nt*8+2*t4, n0+1.
    const int r0 = wrow + g;
    const int r1 = r0 + 8;
    const float m0 = (float)mask[b * 128 + r0];
    const float m1 = (float)mask[b * 128 + r1];
    const float* rt0p = g_A2 + ((size_t)(b * 128 + r0)) * 128;
    const float* rt1p = g_A2 + ((size_t)(b * 128 + r1)) * 128;

#pragma unroll
    for (int nt = 0; nt < 16; nt++) {
        const int n0 = nt * 8 + 2 * t4;
        float2 bs = *(const float2*)&baseCol[(size_t)bc * 128 + n0];
        float2 bi = *(const float2*)&bias[n0];
        float add0 = bs.x + bi.x;
        float add1 = bs.y + bi.y;
        float x00 = acc[nt][0] + add0;
        float x01 = acc[nt][1] + add1;
        float x10 = acc[nt][2] + add0;
        float x11 = acc[nt][3] + add1;
        if (branch) {
            float2 rt0 = *(const float2*)&rt0p[n0];
            float2 rt1 = *(const float2*)&rt1p[n0];
            x00 += rt0.x; x01 += rt0.y;
            x10 += rt1.x; x11 += rt1.y;
        }
        float c0 = fmaxf(fmaxf(x00, 0.0f) * m0, fmaxf(x10, 0.0f) * m1);
        float c1 = fmaxf(fmaxf(x01, 0.0f) * m0, fmaxf(x11, 0.0f) * m1);
        // Reduce max over g (lane bits 2..4)
#pragma unroll
        for (int off = 4; off < 32; off <<= 1) {
            c0 = fmaxf(c0, __shfl_xor_sync(0xFFFFFFFFu, c0, off));
            c1 = fmaxf(c1, __shfl_xor_sync(0xFFFFFFFFu, c1, off));
        }
        if (g == 0) {
            red[warp * 128 + n0] = c0;
            red[warp * 128 + n0 + 1] = c1;
        }
    }

    __syncthreads();
    if (tid < 128) {
        float m = 0.0f;
#pragma unroll
        for (int w = 0; w < 8; w++) m = fmaxf(m, red[w * 128 + tid]);
        out[(size_t)bc * 128 + tid] = m;
    }
}

// ---------------------------------------------------------------------------
// Final GEMM, K=512 split into 4 slices that ARE the concat parts:
//   y=0: clone, y=1: food_relation, y=2: thorn_agg, y=3: clone_agg
// ---------------------------------------------------------------------------
__global__ void __launch_bounds__(256) final_partial_kernel(
    const float* __restrict__ clone,
    const float* __restrict__ food,
    const float* __restrict__ W_agg)
{
    __shared__ float sA[KT * SA_STRIDE];
    __shared__ float sB[KT * 128];

    const int y = blockIdx.y;
    const int m0 = blockIdx.x * 128;
    const float* A;
    switch (y) {
        case 0:  A = clone; break;
        case 1:  A = food; break;
        case 2:  A = g_thorn_agg; break;
        default: A = g_clone_agg; break;
    }
    const float* Bm = W_agg + (size_t)y * 128 * 128;
    float* out = g_partial + (size_t)y * BC * 128;

    float acc[8][8];
    gemm_block_k128(A + (size_t)m0 * 128, 128, Bm, sA, sB, acc);

    const int tid = threadIdx.x;
    const int tx = tid & 15;
    const int ty = tid >> 4;
#pragma unroll
    for (int i = 0; i < 8; i++) {
        int row = m0 + ty * 8 + i;
        *(float4*)&out[(size_t)row * 128 + tx * 8] =
            make_float4(acc[i][0], acc[i][1], acc[i][2], acc[i][3]);
        *(float4*)&out[(size_t)row * 128 + tx * 8 + 4] =
            make_float4(acc[i][4], acc[i][5], acc[i][6], acc[i][7]);
    }
}

// ---------------------------------------------------------------------------
// Combine: out = clone + relu(sum_partials + b_agg)
// ---------------------------------------------------------------------------
__global__ void __launch_bounds__(256) combine_kernel(
    const float* __restrict__ clone,
    const float* __restrict__ b_agg,
    float* __restrict__ out)
{
    int idx = blockIdx.x * 256 + threadIdx.x;
    int n = idx & 127;
    float s = g_partial[idx]
            + g_partial[BC * 128 + idx]
            + g_partial[2 * BC * 128 + idx]
            + g_partial[3 * BC * 128 + idx]
            + b_agg[n];
    out[idx] = clone[idx] + fmaxf(s, 0.0f);
}

// ---------------------------------------------------------------------------
// Launch
// ---------------------------------------------------------------------------
extern "C" void kernel_launch(void* const* d_in, const int* in_sizes, int n_in,
                              void* d_out, int out_size)
{
    const float* food       = (const float*)d_in[0];
    const float* thorn_rel  = (const float*)d_in[1];
    const float* clone      = (const float*)d_in[2];
    const float* clone_rel  = (const float*)d_in[3];
    const int*   thorn_mask = (const int*)d_in[4];
    const int*   clone_mask = (const int*)d_in[5];
    const float* W_thorn    = (const float*)d_in[6];
    const float* b_thorn    = (const float*)d_in[7];
    const float* W_clone    = (const float*)d_in[8];
    const float* b_clone    = (const float*)d_in[9];
    const float* W_agg      = (const float*)d_in[10];
    const float* b_agg      = (const float*)d_in[11];
    float* out = (float*)d_out;

    // 0. Prepack relation weights into TF32 fragment order
    prepack_kernel<<<dim3(64, 2), 256>>>(W_thorn, W_clone);

    // 1. Precompute clone @ {W_thorn[:H], W_clone[:H], W_clone[H:2H]} (exact fp32)
    precompute_kernel<<<dim3(16, 3), 256>>>(clone, W_thorn, W_clone);

    // 2+3. Both relation branches, TF32 tensor cores, one launch
    relation_mma_kernel<<<dim3(BC, 2), 256>>>(thorn_rel, clone_rel,
                                              b_thorn, b_clone,
                                              thorn_mask, clone_mask);

    // 4. Final GEMM (K=512 as 4 slices reading concat sources directly)
    final_partial_kernel<<<dim3(16, 4), 256>>>(clone, food, W_agg);

    // 5. Combine partials + bias, relu, residual add
    combine_kernel<<<(BC * 128) / 256, 256>>>(clone, b_agg, out);
}

// round 4
// speedup vs baseline: 2.9758x; 1.8329x over previous
#include <cuda_runtime.h>
#include <cuda_fp16.h>
#include <cstdint>

#define NB 16
#define BC 2048

// ---------------------------------------------------------------------------
// Scratch (static device globals)
// ---------------------------------------------------------------------------
__device__ float g_base_thorn[BC * 128];
__device__ float g_A1[BC * 128];
__device__ float g_A2[BC * 128];
__device__ float g_thorn_agg[BC * 128];
__device__ float g_clone_agg[BC * 128];
__device__ float g_partial[4 * BC * 128];
// Prepacked fp16 B fragments for mma.m16n8k16, nt-pairs adjacent:
// layout [branch][ ((ks*8 + ntp)*32 + lane)*4 + j ]   (8 ks, 8 ntp, 32 lanes, 4 regs)
__device__ uint32_t g_Bpack[2][8 * 8 * 32 * 4];

// ---------------------------------------------------------------------------
// Prepack B = W (rows are k, cols are n) into fp16 fragment order.
// branch 0: W_thorn rows [H,2H); branch 1: W_clone rows [2H,3H).
// For ks, ntp, lane (g=l>>2, t4=l&3), j:
//   nt = 2*ntp + (j>>1); khalf = (j&1)*8; k = ks*16 + khalf + 2*t4; n = nt*8 + g
//   value = pack_half2(W[k][n], W[k+1][n])
// ---------------------------------------------------------------------------
__global__ void __launch_bounds__(256) prepack_b_kernel(
    const float* __restrict__ W_thorn, const float* __restrict__ W_clone)
{
    int branch = blockIdx.y;
    const float* W = branch ? (W_clone + 2 * 128 * 128) : (W_thorn + 128 * 128);
    int idx = blockIdx.x * 256 + threadIdx.x;     // 0..8191
    int j    = idx & 3;
    int lane = (idx >> 2) & 31;
    int ntp  = (idx >> 7) & 7;
    int ks   = idx >> 10;
    int t4 = lane & 3, g = lane >> 2;
    int nt = 2 * ntp + (j >> 1);
    int k = ks * 16 + (j & 1) * 8 + 2 * t4;
    int n = nt * 8 + g;
    __half2 h = __floats2half2_rn(W[k * 128 + n], W[(k + 1) * 128 + n]);
    g_Bpack[branch][idx] = *(uint32_t*)&h;
}

// ---------------------------------------------------------------------------
// fp32 block GEMM, 64x128 output tile, K=128 (small exact GEMMs).
// ---------------------------------------------------------------------------
#define SA64_STRIDE 68
__device__ __forceinline__ void gemm64_k128(
    const float* __restrict__ A, int lda, const float* __restrict__ Bm,
    float* sA, float* sB, float acc[4][8])
{
    const int tid = threadIdx.x;
    const int tx = tid & 15;
    const int ty = tid >> 4;
#pragma unroll
    for (int i = 0; i < 4; i++)
#pragma unroll
        for (int j = 0; j < 8; j++) acc[i][j] = 0.0f;

    for (int k0 = 0; k0 < 128; k0 += 16) {
        __syncthreads();
#pragma unroll
        for (int r = 0; r < 4; r++) {
            int idx = tid + r * 256;
            int t = idx >> 4;
            int k = idx & 15;
            sA[k * SA64_STRIDE + t] = A[(size_t)t * lda + k0 + k];
        }
#pragma unroll
        for (int r = 0; r < 8; r++) {
            int idx = tid + r * 256;
            int k = idx >> 7;
            int n = idx & 127;
            sB[k * 128 + n] = Bm[(size_t)(k0 + k) * 128 + n];
        }
        __syncthreads();
#pragma unroll
        for (int kk = 0; kk < 16; kk++) {
            float4 av = *(const float4*)&sA[kk * SA64_STRIDE + ty * 4];
            float4 b0 = *(const float4*)&sB[kk * 128 + tx * 8];
            float4 b1 = *(const float4*)&sB[kk * 128 + tx * 8 + 4];
            float a[4] = {av.x, av.y, av.z, av.w};
            float b[8] = {b0.x, b0.y, b0.z, b0.w, b1.x, b1.y, b1.z, b1.w};
#pragma unroll
            for (int i = 0; i < 4; i++)
#pragma unroll
                for (int j = 0; j < 8; j++)
                    acc[i][j] = fmaf(a[i], b[j], acc[i][j]);
        }
    }
}

__device__ __forceinline__ void store_tile64(float* out, int m0, const float acc[4][8]) {
    const int tid = threadIdx.x;
    const int tx = tid & 15;
    const int ty = tid >> 4;
#pragma unroll
    for (int i = 0; i < 4; i++) {
        int row = m0 + ty * 4 + i;
        *(float4*)&out[(size_t)row * 128 + tx * 8] =
            make_float4(acc[i][0], acc[i][1], acc[i][2], acc[i][3]);
        *(float4*)&out[(size_t)row * 128 + tx * 8 + 4] =
            make_float4(acc[i][4], acc[i][5], acc[i][6], acc[i][7]);
    }
}

// ---------------------------------------------------------------------------
// Precompute: clone @ {W_thorn[:H], W_clone[:H], W_clone[H:2H]}, 64-row tiles.
// ---------------------------------------------------------------------------
__global__ void __launch_bounds__(256) precompute_kernel(
    const float* __restrict__ clone,
    const float* __restrict__ W_thorn,
    const float* __restrict__ W_clone)
{
    __shared__ float sA[16 * SA64_STRIDE];
    __shared__ float sB[16 * 128];
    const float* Bm;
    float* out;
    if (blockIdx.y == 0)      { Bm = W_thorn;             out = g_base_thorn; }
    else if (blockIdx.y == 1) { Bm = W_clone;             out = g_A1; }
    else                      { Bm = W_clone + 128 * 128; out = g_A2; }
    const int m0 = blockIdx.x * 64;
    float acc[4][8];
    gemm64_k128(clone + (size_t)m0 * 128, 128, Bm, sA, sB, acc);
    store_tile64(out, m0, acc);
}

// ---------------------------------------------------------------------------
// fp16 mma.m16n8k16 relation kernel. One block per (bc, branch). 8 warps.
// A (rel tile) staged in smem as fp16, padded stride 272B -> conflict-free
// ldmatrix.x4. B read from prepacked gmem fragments (L1-resident) with
// LDG.128 feeding two MMAs.
// ---------------------------------------------------------------------------
#define A_STRIDE_B 272   // bytes per A row in smem (256 data + 16 pad)

__global__ void __launch_bounds__(256) relation_mma_kernel(
    const float* __restrict__ thorn_rel,
    const float* __restrict__ clone_rel,
    const float* __restrict__ b_thorn,
    const float* __restrict__ b_clone,
    const int* __restrict__ thorn_mask,
    const int* __restrict__ clone_mask)
{
    __shared__ __align__(16) char sA[128 * A_STRIDE_B];   // 34816 B
    __shared__ float red[8 * 128];

    const int tid = threadIdx.x;
    const int warp = tid >> 5;
    const int lane = tid & 31;
    const int g = lane >> 2;
    const int t4 = lane & 3;
    const int wrow = warp * 16;
    const int bc = blockIdx.x;
    const int branch = blockIdx.y;
    const int b = bc >> 7;

    const float* rel = branch ? clone_rel : thorn_rel;
    const float* bias = branch ? b_clone : b_thorn;
    const int* mask = branch ? clone_mask : thorn_mask;
    const float* baseCol = branch ? g_A1 : g_base_thorn;
    float* out = branch ? g_clone_agg : g_thorn_agg;
    const uint32_t* __restrict__ Bp = g_Bpack[branch];

    // Stage A: 128x128 fp32 -> fp16 into padded smem rows.
    const float4* At = (const float4*)(rel + (size_t)bc * 128 * 128);
#pragma unroll
    for (int i = 0; i < 16; i++) {
        int idx = tid + i * 256;              // 0..4095
        int row = idx >> 5;
        int q = idx & 31;                     // 4-float group
        float4 v = At[idx];
        __half2 h01 = __floats2half2_rn(v.x, v.y);
        __half2 h23 = __floats2half2_rn(v.z, v.w);
        uint2 pk = make_uint2(*(uint32_t*)&h01, *(uint32_t*)&h23);
        *(uint2*)&sA[row * A_STRIDE_B + q * 8] = pk;
    }
    __syncthreads();

    // ldmatrix base address for this lane (u32 shared-space address)
    uint32_t sA_u32;
    asm("{ .reg .u64 t; cvta.to.shared.u64 t, %1; cvt.u32.u64 %0, t; }"
        : "=r"(sA_u32) : "l"((const void*)sA));
    const int mi = lane >> 3;       // matrix index 0..3
    const int lr = lane & 7;        // row within matrix
    const int arow = wrow + (mi & 1) * 8 + lr;
    const int acolh = (mi >> 1) * 8;      // half-index column offset within k-step
    uint32_t lm_addr = sA_u32 + arow * A_STRIDE_B + acolh * 2;

    float acc[16][4];
#pragma unroll
    for (int nt = 0; nt < 16; nt++)
#pragma unroll
        for (int c = 0; c < 4; c++) acc[nt][c] = 0.0f;

#pragma unroll
    for (int ks = 0; ks < 8; ks++) {
        uint32_t a0, a1, a2, a3;
        asm volatile("ldmatrix.sync.aligned.m8n8.x4.shared.b16 {%0,%1,%2,%3}, [%4];"
                     : "=r"(a0), "=r"(a1), "=r"(a2), "=r"(a3)
                     : "r"(lm_addr + ks * 32));
        const uint32_t* bbase = Bp + (ks * 8) * 128 + lane * 4;
#pragma unroll
        for (int ntp = 0; ntp < 8; ntp++) {
            uint4 bb = *(const uint4*)&bbase[ntp * 128];
            asm volatile(
                "mma.sync.aligned.m16n8k16.row.col.f32.f16.f16.f32 "
                "{%0,%1,%2,%3}, {%4,%5,%6,%7}, {%8,%9}, {%0,%1,%2,%3};"
                : "+f"(acc[2 * ntp][0]), "+f"(acc[2 * ntp][1]),
                  "+f"(acc[2 * ntp][2]), "+f"(acc[2 * ntp][3])
                : "r"(a0), "r"(a1), "r"(a2), "r"(a3), "r"(bb.x), "r"(bb.y));
            asm volatile(
                "mma.sync.aligned.m16n8k16.row.col.f32.f16.f16.f32 "
                "{%0,%1,%2,%3}, {%4,%5,%6,%7}, {%8,%9}, {%0,%1,%2,%3};"
                : "+f"(acc[2 * ntp + 1][0]), "+f"(acc[2 * ntp + 1][1]),
                  "+f"(acc[2 * ntp + 1][2]), "+f"(acc[2 * ntp + 1][3])
                : "r"(a0), "r"(a1), "r"(a2), "r"(a3), "r"(bb.z), "r"(bb.w));
        }
    }

    // Epilogue: rows r0 = wrow+g, r1 = r0+8; cols n0 = nt*8 + 2*t4.
    const int r0 = wrow + g;
    const int r1 = r0 + 8;
    const float m0 = (float)mask[b * 128 + r0];
    const float m1 = (float)mask[b * 128 + r1];
    const float* rt0p = g_A2 + ((size_t)(b * 128 + r0)) * 128;
    const float* rt1p = g_A2 + ((size_t)(b * 128 + r1)) * 128;

#pragma unroll
    for (int nt = 0; nt < 16; nt++) {
        const int n0 = nt * 8 + 2 * t4;
        float2 bs = *(const float2*)&baseCol[(size_t)bc * 128 + n0];
        float2 bi = *(const float2*)&bias[n0];
        float add0 = bs.x + bi.x;
        float add1 = bs.y + bi.y;
        float x00 = acc[nt][0] + add0;
        float x01 = acc[nt][1] + add1;
        float x10 = acc[nt][2] + add0;
        float x11 = acc[nt][3] + add1;
        if (branch) {
            float2 rt0 = *(const float2*)&rt0p[n0];
            float2 rt1 = *(const float2*)&rt1p[n0];
            x00 += rt0.x; x01 += rt0.y;
            x10 += rt1.x; x11 += rt1.y;
        }
        float c0 = fmaxf(fmaxf(x00, 0.0f) * m0, fmaxf(x10, 0.0f) * m1);
        float c1 = fmaxf(fmaxf(x01, 0.0f) * m0, fmaxf(x11, 0.0f) * m1);
#pragma unroll
        for (int off = 4; off < 32; off <<= 1) {
            c0 = fmaxf(c0, __shfl_xor_sync(0xFFFFFFFFu, c0, off));
            c1 = fmaxf(c1, __shfl_xor_sync(0xFFFFFFFFu, c1, off));
        }
        if (g == 0) {
            red[warp * 128 + n0] = c0;
            red[warp * 128 + n0 + 1] = c1;
        }
    }

    __syncthreads();
    if (tid < 128) {
        float m = 0.0f;
#pragma unroll
        for (int w = 0; w < 8; w++) m = fmaxf(m, red[w * 128 + tid]);
        out[(size_t)bc * 128 + tid] = m;
    }
}

// ---------------------------------------------------------------------------
// Final GEMM: K=512 as 4 slices = concat sources directly. 64-row tiles.
// ---------------------------------------------------------------------------
__global__ void __launch_bounds__(256) final_partial_kernel(
    const float* __restrict__ clone,
    const float* __restrict__ food,
    const float* __restrict__ W_agg)
{
    __shared__ float sA[16 * SA64_STRIDE];
    __shared__ float sB[16 * 128];
    const int y = blockIdx.y;
    const int m0 = blockIdx.x * 64;
    const float* A;
    switch (y) {
        case 0:  A = clone; break;
        case 1:  A = food; break;
        case 2:  A = g_thorn_agg; break;
        default: A = g_clone_agg; break;
    }
    float acc[4][8];
    gemm64_k128(A + (size_t)m0 * 128, 128, W_agg + (size_t)y * 128 * 128, sA, sB, acc);
    store_tile64(g_partial + (size_t)y * BC * 128, m0, acc);
}

// ---------------------------------------------------------------------------
// Combine: out = clone + relu(sum_partials + b_agg)
// ---------------------------------------------------------------------------
__global__ void __launch_bounds__(256) combine_kernel(
    const float* __restrict__ clone,
    const float* __restrict__ b_agg,
    float* __restrict__ out)
{
    int idx = blockIdx.x * 256 + threadIdx.x;
    int n = idx & 127;
    float s = g_partial[idx] + g_partial[BC * 128 + idx]
            + g_partial[2 * BC * 128 + idx] + g_partial[3 * BC * 128 + idx] + b_agg[n];
    out[idx] = clone[idx] + fmaxf(s, 0.0f);
}

// ---------------------------------------------------------------------------
// Launch
// ---------------------------------------------------------------------------
extern "C" void kernel_launch(void* const* d_in, const int* in_sizes, int n_in,
                              void* d_out, int out_size)
{
    const float* food       = (const float*)d_in[0];
    const float* thorn_rel  = (const float*)d_in[1];
    const float* clone      = (const float*)d_in[2];
    const float* clone_rel  = (const float*)d_in[3];
    const int*   thorn_mask = (const int*)d_in[4];
    const int*   clone_mask = (const int*)d_in[5];
    const float* W_thorn    = (const float*)d_in[6];
    const float* b_thorn    = (const float*)d_in[7];
    const float* W_clone    = (const float*)d_in[8];
    const float* b_clone    = (const float*)d_in[9];
    const float* W_agg      = (const float*)d_in[10];
    const float* b_agg      = (const float*)d_in[11];
    float* out = (float*)d_out;

    prepack_b_kernel<<<dim3(32, 2), 256>>>(W_thorn, W_clone);
    precompute_kernel<<<dim3(32, 3), 256>>>(clone, W_thorn, W_clone);
    relation_mma_kernel<<<dim3(BC, 2), 256>>>(thorn_rel, clone_rel,
                                              b_thorn, b_clone,
                                              thorn_mask, clone_mask);
    final_partial_kernel<<<dim3(32, 4), 256>>>(clone, food, W_agg);
    combine_kernel<<<(BC * 128) / 256, 256>>>(clone, b_agg, out);
}